// round 5
// baseline (speedup 1.0000x reference)
#include <cuda_runtime.h>

#define NN 50000
#define NE 800000
#define DI 128
#define DH 128
#define DO 64
#define SPAD 132   // padded smem row stride (floats): 132 % 8 == 4 -> conflict-optimal float4 reads

// Scratch (device globals: no allocations allowed). 16B-aligned for float4 / red.v4 access.
__device__ __align__(16) float g_agg[NN * DI];   // layer-1 aggregate; reused (first NN*DO) for layer-2
__device__ __align__(16) float g_h[NN * DH];     // layer-1 output
__device__ __align__(16) float g_p[NN * DO];     // h @ Wl2^T (pre-aggregation, layer 2)
__device__ __align__(16) float g_cnt[NN];        // in-degree
__device__ int g_ei_is32;                        // 1 if edge_index buffer is int32, 0 if int64

// ---------------- packed fp32x2 helpers ----------------
__device__ __forceinline__ void fma2(unsigned long long &d, unsigned long long a, unsigned long long b) {
    asm("fma.rn.f32x2 %0, %1, %2, %0;" : "+l"(d) : "l"(a), "l"(b));
}
__device__ __forceinline__ float2 unpack2(unsigned long long v) {
    float2 r;
    asm("mov.b64 {%0, %1}, %2;" : "=f"(r.x), "=f"(r.y) : "l"(v));
    return r;
}

// ---------------- edge-index dtype probe (1 thread) ----------------
// If the buffer really holds int64 indices, every 8-byte word is in [0, NN).
// If it holds int32, an 8-byte read packs two indices -> value >= 2^32 (unless
// the high index is exactly 0; probability over 64 probes is negligible).
__global__ void k_detect_ei(const void* ei) {
    const long long* p = (const long long*)ei;
    int is32 = 0;
    for (int i = 0; i < 64; i++) {
        long long v = p[i];
        if (v < 0 || v >= NN) { is32 = 1; break; }
    }
    g_ei_is32 = is32;
}

__device__ __forceinline__ void load_edge(const void* ei, int e, int is32, int& src, int& dst) {
    if (is32) {
        const int* p = (const int*)ei;
        src = p[e]; dst = p[NE + e];
    } else {
        const long long* p = (const long long*)ei;
        src = (int)p[e]; dst = (int)p[NE + e];
    }
}

// ---------------- zero kernels ----------------
__global__ void k_zero1() {
    int i = blockIdx.x * blockDim.x + threadIdx.x;
    if (i < NN * DI / 4) ((float4*)g_agg)[i] = make_float4(0.f, 0.f, 0.f, 0.f);
    if (i < NN) g_cnt[i] = 0.f;
}
__global__ void k_zero2() {
    int i = blockIdx.x * blockDim.x + threadIdx.x;
    if (i < NN * DO / 4) ((float4*)g_agg)[i] = make_float4(0.f, 0.f, 0.f, 0.f);
}

// ---------------- edge scatter (layer 1): x[src] -> agg[dst], degree count ----------------
__global__ void k_scatter_x(const float* __restrict__ x, const void* __restrict__ ei) {
    int gw   = (blockIdx.x * blockDim.x + threadIdx.x) >> 5;
    int lane = threadIdx.x & 31;
    int nw   = (gridDim.x * blockDim.x) >> 5;
    const int is32 = g_ei_is32;
    for (int e = gw; e < NE; e += nw) {
        int src, dst;
        load_edge(ei, e, is32, src, dst);
        if ((unsigned)src >= NN || (unsigned)dst >= NN) continue;  // safety net
        float4 v = *(const float4*)(x + (size_t)src * DI + lane * 4);
        float* p = g_agg + (size_t)dst * DI + lane * 4;
        asm volatile("red.global.add.v4.f32 [%0], {%1,%2,%3,%4};"
                     :: "l"(p), "f"(v.x), "f"(v.y), "f"(v.z), "f"(v.w) : "memory");
        if (lane == 0) {
            float* c = g_cnt + dst;
            asm volatile("red.global.add.f32 [%0], %1;" :: "l"(c), "f"(1.0f) : "memory");
        }
    }
}

// ---------------- edge scatter (layer 2): p[src] (64-dim) -> agg[dst] ----------------
__global__ void k_scatter_p(const void* __restrict__ ei) {
    int gw   = (blockIdx.x * blockDim.x + threadIdx.x) >> 5;
    int lane = threadIdx.x & 31;
    int nw   = (gridDim.x * blockDim.x) >> 5;
    const int is32 = g_ei_is32;
    for (int e = gw; e < NE; e += nw) {
        int src, dst;
        load_edge(ei, e, is32, src, dst);
        if ((unsigned)src >= NN || (unsigned)dst >= NN) continue;
        float2 v = *(const float2*)(g_p + (size_t)src * DO + lane * 2);
        float* p = g_agg + (size_t)dst * DO + lane * 2;
        asm volatile("red.global.add.v2.f32 [%0], {%1,%2};"
                     :: "l"(p), "f"(v.x), "f"(v.y) : "memory");
    }
}

// ---------------- layer-1 fused GEMM: h = relu(mean @ Wl1^T + bl1 + x @ Wr1^T) ----------------
// Block: 256 threads, tile = 64 nodes x 128 outputs. f32x2 packed math.
__global__ void __launch_bounds__(256, 1) k_gemm1(
    const float* __restrict__ x, const float* __restrict__ Wl,
    const float* __restrict__ bl, const float* __restrict__ Wr)
{
    extern __shared__ float smem[];
    float* sWl = smem;                  // [128][SPAD]
    float* sWr = sWl + DH * SPAD;       // [128][SPAD]
    float* sXm = sWr + DH * SPAD;       // [64][SPAD]   mean tile
    float* sXx = sXm + 64 * SPAD;       // [64][SPAD]   x tile

    const int tid   = threadIdx.x;
    const int node0 = blockIdx.x * 64;
    const int r     = tid >> 5;
    const int k4    = (tid & 31) * 4;

    // stage weights (row-major, padded stride): coalesced loads, conflict-free stores
    #pragma unroll
    for (int it = 0; it < 16; it++) {
        int j = it * 8 + r;
        *(float4*)(sWl + j * SPAD + k4) = *(const float4*)(Wl + j * DI + k4);
        *(float4*)(sWr + j * SPAD + k4) = *(const float4*)(Wr + j * DI + k4);
    }
    // stage input tiles (mean = agg * 1/max(cnt,1))
    #pragma unroll
    for (int it = 0; it < 8; it++) {
        int nl = it * 8 + r;
        int n  = node0 + nl;
        float4 xm = make_float4(0.f, 0.f, 0.f, 0.f), xx = xm;
        if (n < NN) {
            float inv = 1.0f / fmaxf(g_cnt[n], 1.0f);
            float4 a = *(const float4*)(g_agg + (size_t)n * DI + k4);
            xm = make_float4(a.x * inv, a.y * inv, a.z * inv, a.w * inv);
            xx = *(const float4*)(x + (size_t)n * DI + k4);
        }
        *(float4*)(sXm + nl * SPAD + k4) = xm;
        *(float4*)(sXx + nl * SPAD + k4) = xx;
    }
    __syncthreads();

    const int lane = tid & 31;
    const int jl   = lane & 15;                       // output lane: j = jl + 16*jj
    const int nb   = ((tid >> 5) * 2 + (lane >> 4)) * 4;  // local node base (4 nodes)

    unsigned long long acc[4][8];
    #pragma unroll
    for (int nn = 0; nn < 4; nn++)
        #pragma unroll
        for (int jj = 0; jj < 8; jj++) acc[nn][jj] = 0ull;

    #pragma unroll 2
    for (int k = 0; k < DI; k += 4) {
        ulonglong2 xm[4], xx[4];
        #pragma unroll
        for (int nn = 0; nn < 4; nn++) {
            xm[nn] = *(const ulonglong2*)(sXm + (nb + nn) * SPAD + k);
            xx[nn] = *(const ulonglong2*)(sXx + (nb + nn) * SPAD + k);
        }
        #pragma unroll
        for (int jj = 0; jj < 8; jj++) {
            int j = jl + 16 * jj;
            ulonglong2 wl = *(const ulonglong2*)(sWl + j * SPAD + k);
            ulonglong2 wr = *(const ulonglong2*)(sWr + j * SPAD + k);
            #pragma unroll
            for (int nn = 0; nn < 4; nn++) {
                fma2(acc[nn][jj], xm[nn].x, wl.x);
                fma2(acc[nn][jj], xm[nn].y, wl.y);
                fma2(acc[nn][jj], xx[nn].x, wr.x);
                fma2(acc[nn][jj], xx[nn].y, wr.y);
            }
        }
    }

    #pragma unroll
    for (int nn = 0; nn < 4; nn++) {
        int n = node0 + nb + nn;
        if (n < NN) {
            #pragma unroll
            for (int jj = 0; jj < 8; jj++) {
                int j = jl + 16 * jj;
                float2 s = unpack2(acc[nn][jj]);
                float v = s.x + s.y + bl[j];
                g_h[(size_t)n * DH + j] = fmaxf(v, 0.0f);
            }
        }
    }
}

// ---------------- layer-2 GEMMs (in=128, out=64) ----------------
// FINAL=false: g_p = h @ Wl2^T
// FINAL=true : out = relu(agg2*inv + bl2 + h @ Wr2^T)
template<bool FINAL>
__global__ void __launch_bounds__(256) k_gemmB(
    const float* __restrict__ W, const float* __restrict__ bias, float* __restrict__ out)
{
    extern __shared__ float smem[];
    float* sW = smem;                 // [64][SPAD]
    float* sX = sW + DO * SPAD;       // [64][SPAD]

    const int tid   = threadIdx.x;
    const int node0 = blockIdx.x * 64;
    const int r     = tid >> 5;
    const int k4    = (tid & 31) * 4;

    #pragma unroll
    for (int it = 0; it < 8; it++) {
        int j = it * 8 + r;
        *(float4*)(sW + j * SPAD + k4) = *(const float4*)(W + j * DH + k4);
        int n = node0 + j;  // same index pattern for the 64-node tile
        float4 h4 = make_float4(0.f, 0.f, 0.f, 0.f);
        if (n < NN) h4 = *(const float4*)(g_h + (size_t)n * DH + k4);
        *(float4*)(sX + j * SPAD + k4) = h4;
    }
    __syncthreads();

    const int lane = tid & 31;
    const int jl   = lane & 15;
    const int nb   = ((tid >> 5) * 2 + (lane >> 4)) * 4;

    unsigned long long acc[4][4];
    #pragma unroll
    for (int nn = 0; nn < 4; nn++)
        #pragma unroll
        for (int jj = 0; jj < 4; jj++) acc[nn][jj] = 0ull;

    #pragma unroll 2
    for (int k = 0; k < DH; k += 4) {
        ulonglong2 xv[4];
        #pragma unroll
        for (int nn = 0; nn < 4; nn++)
            xv[nn] = *(const ulonglong2*)(sX + (nb + nn) * SPAD + k);
        #pragma unroll
        for (int jj = 0; jj < 4; jj++) {
            int j = jl + 16 * jj;
            ulonglong2 wv = *(const ulonglong2*)(sW + j * SPAD + k);
            #pragma unroll
            for (int nn = 0; nn < 4; nn++) {
                fma2(acc[nn][jj], xv[nn].x, wv.x);
                fma2(acc[nn][jj], xv[nn].y, wv.y);
            }
        }
    }

    #pragma unroll
    for (int nn = 0; nn < 4; nn++) {
        int n = node0 + nb + nn;
        if (n < NN) {
            float inv = 0.f;
            if (FINAL) inv = 1.0f / fmaxf(g_cnt[n], 1.0f);
            #pragma unroll
            for (int jj = 0; jj < 4; jj++) {
                int j = jl + 16 * jj;
                float2 s = unpack2(acc[nn][jj]);
                float v = s.x + s.y;
                if (FINAL) {
                    v += g_agg[(size_t)n * DO + j] * inv + bias[j];
                    out[(size_t)n * DO + j] = fmaxf(v, 0.0f);
                } else {
                    g_p[(size_t)n * DO + j] = v;
                }
            }
        }
    }
}

// ---------------- log_softmax over 64 cols, in place ----------------
__global__ void k_lsm(float* __restrict__ out) {
    int gw   = (blockIdx.x * blockDim.x + threadIdx.x) >> 5;
    int lane = threadIdx.x & 31;
    if (gw >= NN) return;
    float2 v = *(float2*)(out + (size_t)gw * DO + lane * 2);
    float m = fmaxf(v.x, v.y);
    #pragma unroll
    for (int o = 16; o > 0; o >>= 1) m = fmaxf(m, __shfl_xor_sync(0xffffffffu, m, o));
    float s = expf(v.x - m) + expf(v.y - m);
    #pragma unroll
    for (int o = 16; o > 0; o >>= 1) s += __shfl_xor_sync(0xffffffffu, s, o);
    float lse = m + logf(s);
    *(float2*)(out + (size_t)gw * DO + lane * 2) = make_float2(v.x - lse, v.y - lse);
}

// ---------------- launch ----------------
extern "C" void kernel_launch(void* const* d_in, const int* in_sizes, int n_in,
                              void* d_out, int out_size) {
    const float* x   = (const float*)d_in[0];
    const void*  ei  = d_in[1];
    const float* Wl1 = (const float*)d_in[2];
    const float* bl1 = (const float*)d_in[3];
    const float* Wr1 = (const float*)d_in[4];
    const float* Wl2 = (const float*)d_in[5];
    const float* bl2 = (const float*)d_in[6];
    const float* Wr2 = (const float*)d_in[7];
    float* out = (float*)d_out;

    const int SM1 = (2 * DH * SPAD + 2 * 64 * SPAD) * (int)sizeof(float);  // 202752 B
    const int SM2 = (2 * 64 * SPAD) * (int)sizeof(float);                  // 67584 B
    (void)cudaFuncSetAttribute(k_gemm1,        cudaFuncAttributeMaxDynamicSharedMemorySize, SM1);
    (void)cudaFuncSetAttribute(k_gemmB<false>, cudaFuncAttributeMaxDynamicSharedMemorySize, SM2);
    (void)cudaFuncSetAttribute(k_gemmB<true>,  cudaFuncAttributeMaxDynamicSharedMemorySize, SM2);

    const int GN = (NN + 63) / 64;

    k_detect_ei<<<1, 1>>>(ei);
    k_zero1<<<(NN * DI / 4 + 255) / 256, 256>>>();
    k_scatter_x<<<12500, 256>>>(x, ei);
    k_gemm1<<<GN, 256, SM1>>>(x, Wl1, bl1, Wr1);
    k_gemmB<false><<<GN, 256, SM2>>>(Wl2, nullptr, nullptr);
    k_zero2<<<(NN * DO / 4 + 255) / 256, 256>>>();
    k_scatter_p<<<12500, 256>>>(ei);
    k_gemmB<true><<<GN, 256, SM2>>>(Wr2, bl2, out);
    k_lsm<<<(NN * 32 + 255) / 256, 256>>>(out);
}

// round 6
// speedup vs baseline: 1.0224x; 1.0224x over previous
#include <cuda_runtime.h>

#define NN 50000
#define NE 800000
#define DI 128
#define DH 128
#define DO 64
#define SPAD 132   // padded smem row stride (floats)

// Scratch (device globals). 16B-aligned for float4 / red.v4 access.
__device__ __align__(16) float g_agg[NN * DI];
__device__ __align__(16) float g_h[NN * DH];
__device__ __align__(16) float g_p[NN * DO];
__device__ __align__(16) float g_cnt[NN];
__device__ int g_ei_is32;

// ---------------- packed fp32x2 helpers ----------------
__device__ __forceinline__ void fma2(unsigned long long &d, unsigned long long a, unsigned long long b) {
    asm("fma.rn.f32x2 %0, %1, %2, %0;" : "+l"(d) : "l"(a), "l"(b));
}
__device__ __forceinline__ float2 unpack2(unsigned long long v) {
    float2 r;
    asm("mov.b64 {%0, %1}, %2;" : "=f"(r.x), "=f"(r.y) : "l"(v));
    return r;
}

// ---------------- edge-index dtype probe ----------------
__global__ void k_detect_ei(const void* ei) {
    const long long* p = (const long long*)ei;
    int is32 = 0;
    for (int i = 0; i < 64; i++) {
        long long v = p[i];
        if (v < 0 || v >= NN) { is32 = 1; break; }
    }
    g_ei_is32 = is32;
}

__device__ __forceinline__ void load_edge(const void* ei, int e, int is32, int& src, int& dst) {
    if (is32) {
        const int* p = (const int*)ei;
        src = p[e]; dst = p[NE + e];
    } else {
        const long long* p = (const long long*)ei;
        src = (int)p[e]; dst = (int)p[NE + e];
    }
}

// ---------------- zero kernels ----------------
__global__ void k_zero1() {
    int i = blockIdx.x * blockDim.x + threadIdx.x;
    if (i < NN * DI / 4) ((float4*)g_agg)[i] = make_float4(0.f, 0.f, 0.f, 0.f);
    if (i < NN) g_cnt[i] = 0.f;
}
__global__ void k_zero2() {
    int i = blockIdx.x * blockDim.x + threadIdx.x;
    if (i < NN * DO / 4) ((float4*)g_agg)[i] = make_float4(0.f, 0.f, 0.f, 0.f);
}

// ---------------- edge scatter (layer 1), 2-edge unroll ----------------
__global__ void k_scatter_x(const float* __restrict__ x, const void* __restrict__ ei) {
    int gw   = (blockIdx.x * blockDim.x + threadIdx.x) >> 5;
    int lane = threadIdx.x & 31;
    int nw   = (gridDim.x * blockDim.x) >> 5;
    const int is32 = g_ei_is32;
    for (int e = gw; e < NE; e += 2 * nw) {
        int e1 = e + nw;
        int s0, d0, s1 = 0, d1 = 0;
        load_edge(ei, e, is32, s0, d0);
        bool ok0 = (unsigned)s0 < NN && (unsigned)d0 < NN;
        bool has1 = e1 < NE, ok1 = false;
        if (has1) { load_edge(ei, e1, is32, s1, d1); ok1 = (unsigned)s1 < NN && (unsigned)d1 < NN; }
        float4 v0 = make_float4(0.f,0.f,0.f,0.f), v1 = v0;
        if (ok0) v0 = *(const float4*)(x + (size_t)s0 * DI + lane * 4);
        if (ok1) v1 = *(const float4*)(x + (size_t)s1 * DI + lane * 4);
        if (ok0) {
            float* p = g_agg + (size_t)d0 * DI + lane * 4;
            asm volatile("red.global.add.v4.f32 [%0], {%1,%2,%3,%4};"
                         :: "l"(p), "f"(v0.x), "f"(v0.y), "f"(v0.z), "f"(v0.w) : "memory");
            if (lane == 0)
                asm volatile("red.global.add.f32 [%0], %1;" :: "l"(g_cnt + d0), "f"(1.0f) : "memory");
        }
        if (ok1) {
            float* p = g_agg + (size_t)d1 * DI + lane * 4;
            asm volatile("red.global.add.v4.f32 [%0], {%1,%2,%3,%4};"
                         :: "l"(p), "f"(v1.x), "f"(v1.y), "f"(v1.z), "f"(v1.w) : "memory");
            if (lane == 0)
                asm volatile("red.global.add.f32 [%0], %1;" :: "l"(g_cnt + d1), "f"(1.0f) : "memory");
        }
    }
}

// ---------------- edge scatter (layer 2), 2-edge unroll ----------------
__global__ void k_scatter_p(const void* __restrict__ ei) {
    int gw   = (blockIdx.x * blockDim.x + threadIdx.x) >> 5;
    int lane = threadIdx.x & 31;
    int nw   = (gridDim.x * blockDim.x) >> 5;
    const int is32 = g_ei_is32;
    for (int e = gw; e < NE; e += 2 * nw) {
        int e1 = e + nw;
        int s0, d0, s1 = 0, d1 = 0;
        load_edge(ei, e, is32, s0, d0);
        bool ok0 = (unsigned)s0 < NN && (unsigned)d0 < NN;
        bool has1 = e1 < NE, ok1 = false;
        if (has1) { load_edge(ei, e1, is32, s1, d1); ok1 = (unsigned)s1 < NN && (unsigned)d1 < NN; }
        float2 v0 = make_float2(0.f,0.f), v1 = v0;
        if (ok0) v0 = *(const float2*)(g_p + (size_t)s0 * DO + lane * 2);
        if (ok1) v1 = *(const float2*)(g_p + (size_t)s1 * DO + lane * 2);
        if (ok0) {
            float* p = g_agg + (size_t)d0 * DO + lane * 2;
            asm volatile("red.global.add.v2.f32 [%0], {%1,%2};"
                         :: "l"(p), "f"(v0.x), "f"(v0.y) : "memory");
        }
        if (ok1) {
            float* p = g_agg + (size_t)d1 * DO + lane * 2;
            asm volatile("red.global.add.v2.f32 [%0], {%1,%2};"
                         :: "l"(p), "f"(v1.x), "f"(v1.y) : "memory");
        }
    }
}

// ---------------- layer-1 fused GEMM: h = relu(mean @ Wl1^T + bl1 + x @ Wr1^T) ----------------
// 512 threads, tile 64 nodes x 128 outputs; per thread: 4 nodes x 4 outputs (traffic-optimal).
__global__ void __launch_bounds__(512, 1) k_gemm1(
    const float* __restrict__ x, const float* __restrict__ Wl,
    const float* __restrict__ bl, const float* __restrict__ Wr)
{
    extern __shared__ float smem[];
    float* sWl = smem;                  // [128][SPAD]
    float* sWr = sWl + DH * SPAD;       // [128][SPAD]
    float* sXm = sWr + DH * SPAD;       // [64][SPAD]
    float* sXx = sXm + 64 * SPAD;       // [64][SPAD]

    const int tid   = threadIdx.x;
    const int node0 = blockIdx.x * 64;
    const int r     = tid >> 5;          // warp 0..15
    const int k4    = (tid & 31) * 4;

    #pragma unroll
    for (int it = 0; it < 8; it++) {
        int j = it * 16 + r;
        *(float4*)(sWl + j * SPAD + k4) = *(const float4*)(Wl + j * DI + k4);
        *(float4*)(sWr + j * SPAD + k4) = *(const float4*)(Wr + j * DI + k4);
    }
    #pragma unroll
    for (int it = 0; it < 4; it++) {
        int nl = it * 16 + r;
        int n  = node0 + nl;
        float4 xm = make_float4(0.f, 0.f, 0.f, 0.f), xx = xm;
        if (n < NN) {
            float inv = 1.0f / fmaxf(g_cnt[n], 1.0f);
            float4 a = *(const float4*)(g_agg + (size_t)n * DI + k4);
            xm = make_float4(a.x * inv, a.y * inv, a.z * inv, a.w * inv);
            xx = *(const float4*)(x + (size_t)n * DI + k4);
        }
        *(float4*)(sXm + nl * SPAD + k4) = xm;
        *(float4*)(sXx + nl * SPAD + k4) = xx;
    }
    __syncthreads();

    const int lane = tid & 31;
    const int jl   = lane & 15;               // j = jl + 16*(jo + jj)
    const int jo   = (r >> 3) * 4;            // 0 or 4
    const int nb   = ((r & 7) * 2 + (lane >> 4)) * 4;  // node base: 4 nodes

    unsigned long long acc[4][4];
    #pragma unroll
    for (int nn = 0; nn < 4; nn++)
        #pragma unroll
        for (int jj = 0; jj < 4; jj++) acc[nn][jj] = 0ull;

    #pragma unroll 2
    for (int k = 0; k < DI; k += 4) {
        ulonglong2 xm[4], xx[4];
        #pragma unroll
        for (int nn = 0; nn < 4; nn++) {
            xm[nn] = *(const ulonglong2*)(sXm + (nb + nn) * SPAD + k);
            xx[nn] = *(const ulonglong2*)(sXx + (nb + nn) * SPAD + k);
        }
        #pragma unroll
        for (int jj = 0; jj < 4; jj++) {
            int j = jl + 16 * (jo + jj);
            ulonglong2 wl = *(const ulonglong2*)(sWl + j * SPAD + k);
            ulonglong2 wr = *(const ulonglong2*)(sWr + j * SPAD + k);
            #pragma unroll
            for (int nn = 0; nn < 4; nn++) {
                fma2(acc[nn][jj], xm[nn].x, wl.x);
                fma2(acc[nn][jj], xm[nn].y, wl.y);
                fma2(acc[nn][jj], xx[nn].x, wr.x);
                fma2(acc[nn][jj], xx[nn].y, wr.y);
            }
        }
    }

    #pragma unroll
    for (int nn = 0; nn < 4; nn++) {
        int n = node0 + nb + nn;
        if (n < NN) {
            #pragma unroll
            for (int jj = 0; jj < 4; jj++) {
                int j = jl + 16 * (jo + jj);
                float2 s = unpack2(acc[nn][jj]);
                float v = s.x + s.y + bl[j];
                g_h[(size_t)n * DH + j] = fmaxf(v, 0.0f);
            }
        }
    }
}

// ---------------- layer-2 GEMMs (in=128, out=64) ----------------
// FINAL=false: g_p = h @ Wl2^T
// FINAL=true : out = log_softmax(relu(agg2*inv + bl2 + h @ Wr2^T))  (lsm fused)
template<bool FINAL>
__global__ void __launch_bounds__(256) k_gemmB(
    const float* __restrict__ W, const float* __restrict__ bias, float* __restrict__ out)
{
    extern __shared__ float smem[];
    float* sW = smem;                 // [64][SPAD]
    float* sX = sW + DO * SPAD;       // [64][SPAD]

    const int tid   = threadIdx.x;
    const int node0 = blockIdx.x * 64;
    const int r     = tid >> 5;
    const int k4    = (tid & 31) * 4;

    #pragma unroll
    for (int it = 0; it < 8; it++) {
        int j = it * 8 + r;
        *(float4*)(sW + j * SPAD + k4) = *(const float4*)(W + j * DH + k4);
        int n = node0 + j;
        float4 h4 = make_float4(0.f, 0.f, 0.f, 0.f);
        if (n < NN) h4 = *(const float4*)(g_h + (size_t)n * DH + k4);
        *(float4*)(sX + j * SPAD + k4) = h4;
    }
    __syncthreads();

    const int lane = tid & 31;
    const int jl   = lane & 15;
    const int nb   = ((tid >> 5) * 2 + (lane >> 4)) * 4;

    unsigned long long acc[4][4];
    #pragma unroll
    for (int nn = 0; nn < 4; nn++)
        #pragma unroll
        for (int jj = 0; jj < 4; jj++) acc[nn][jj] = 0ull;

    #pragma unroll 2
    for (int k = 0; k < DH; k += 4) {
        ulonglong2 xv[4];
        #pragma unroll
        for (int nn = 0; nn < 4; nn++)
            xv[nn] = *(const ulonglong2*)(sX + (nb + nn) * SPAD + k);
        #pragma unroll
        for (int jj = 0; jj < 4; jj++) {
            int j = jl + 16 * jj;
            ulonglong2 wv = *(const ulonglong2*)(sW + j * SPAD + k);
            #pragma unroll
            for (int nn = 0; nn < 4; nn++) {
                fma2(acc[nn][jj], xv[nn].x, wv.x);
                fma2(acc[nn][jj], xv[nn].y, wv.y);
            }
        }
    }

    #pragma unroll
    for (int nn = 0; nn < 4; nn++) {
        int n = node0 + nb + nn;
        bool valid = (n < NN);
        if (FINAL) {
            // compute relu'd logits for this node's 4 outputs
            float v[4];
            float inv = 0.f;
            if (valid) inv = 1.0f / fmaxf(g_cnt[n], 1.0f);
            #pragma unroll
            for (int jj = 0; jj < 4; jj++) {
                int j = jl + 16 * jj;
                float2 s = unpack2(acc[nn][jj]);
                float t = s.x + s.y;
                if (valid) t += g_agg[(size_t)n * DO + j] * inv + bias[j];
                v[jj] = valid ? fmaxf(t, 0.0f) : 0.0f;
            }
            // fused log_softmax: node's 64 outputs live in 16 lanes x 4 regs
            float m = fmaxf(fmaxf(v[0], v[1]), fmaxf(v[2], v[3]));
            #pragma unroll
            for (int o = 8; o > 0; o >>= 1) m = fmaxf(m, __shfl_xor_sync(0xffffffffu, m, o));
            float ss = expf(v[0] - m) + expf(v[1] - m) + expf(v[2] - m) + expf(v[3] - m);
            #pragma unroll
            for (int o = 8; o > 0; o >>= 1) ss += __shfl_xor_sync(0xffffffffu, ss, o);
            float lse = m + logf(ss);
            if (valid) {
                #pragma unroll
                for (int jj = 0; jj < 4; jj++) {
                    int j = jl + 16 * jj;
                    out[(size_t)n * DO + j] = v[jj] - lse;
                }
            }
        } else {
            if (valid) {
                #pragma unroll
                for (int jj = 0; jj < 4; jj++) {
                    int j = jl + 16 * jj;
                    float2 s = unpack2(acc[nn][jj]);
                    g_p[(size_t)n * DO + j] = s.x + s.y;
                }
            }
        }
    }
}

// ---------------- launch ----------------
extern "C" void kernel_launch(void* const* d_in, const int* in_sizes, int n_in,
                              void* d_out, int out_size) {
    const float* x   = (const float*)d_in[0];
    const void*  ei  = d_in[1];
    const float* Wl1 = (const float*)d_in[2];
    const float* bl1 = (const float*)d_in[3];
    const float* Wr1 = (const float*)d_in[4];
    const float* Wl2 = (const float*)d_in[5];
    const float* bl2 = (const float*)d_in[6];
    const float* Wr2 = (const float*)d_in[7];
    float* out = (float*)d_out;

    const int SM1 = (2 * DH * SPAD + 2 * 64 * SPAD) * (int)sizeof(float);  // 202752 B
    const int SM2 = (2 * 64 * SPAD) * (int)sizeof(float);                  // 67584 B
    (void)cudaFuncSetAttribute(k_gemm1,        cudaFuncAttributeMaxDynamicSharedMemorySize, SM1);
    (void)cudaFuncSetAttribute(k_gemmB<false>, cudaFuncAttributeMaxDynamicSharedMemorySize, SM2);
    (void)cudaFuncSetAttribute(k_gemmB<true>,  cudaFuncAttributeMaxDynamicSharedMemorySize, SM2);

    const int GN = (NN + 63) / 64;

    k_detect_ei<<<1, 1>>>(ei);
    k_zero1<<<(NN * DI / 4 + 255) / 256, 256>>>();
    k_scatter_x<<<12500, 256>>>(x, ei);
    k_gemm1<<<GN, 512, SM1>>>(x, Wl1, bl1, Wr1);
    k_gemmB<false><<<GN, 256, SM2>>>(Wl2, nullptr, nullptr);
    k_zero2<<<(NN * DO / 4 + 255) / 256, 256>>>();
    k_scatter_p<<<12500, 256>>>(ei);
    k_gemmB<true><<<GN, 256, SM2>>>(Wr2, bl2, out);
}

// round 7
// speedup vs baseline: 1.3302x; 1.3011x over previous
#include <cuda_runtime.h>

#define NN 50000
#define NE 800000
#define DI 128
#define DH 128
#define DO 64
#define SPAD 132   // padded smem row stride (floats)

// Scratch (device globals). 16B-aligned for float4 access.
__device__ __align__(16) float g_agg[NN * DI];   // mean-aggregated features (l1: 128d, l2: first 64d)
__device__ __align__(16) float g_h[NN * DH];     // layer-1 output
__device__ __align__(16) float g_p[NN * DO];     // h @ Wl2^T (pre-aggregation)
__device__ int g_rp[NN + 1];                     // CSR row ptr (by dst)
__device__ int g_cur[NN];                        // degree, then cursor
__device__ int g_srt[NE];                        // src ids sorted by dst
__device__ int g_blksum[256];                    // scan partials
__device__ int g_ei_is32;

// ---------------- packed fp32x2 helpers ----------------
__device__ __forceinline__ void fma2(unsigned long long &d, unsigned long long a, unsigned long long b) {
    asm("fma.rn.f32x2 %0, %1, %2, %0;" : "+l"(d) : "l"(a), "l"(b));
}
__device__ __forceinline__ float2 unpack2(unsigned long long v) {
    float2 r;
    asm("mov.b64 {%0, %1}, %2;" : "=f"(r.x), "=f"(r.y) : "l"(v));
    return r;
}

// ---------------- edge-index dtype probe ----------------
__global__ void k_detect_ei(const void* ei) {
    const long long* p = (const long long*)ei;
    int is32 = 0;
    for (int i = 0; i < 64; i++) {
        long long v = p[i];
        if (v < 0 || v >= NN) { is32 = 1; break; }
    }
    g_ei_is32 = is32;
}

__device__ __forceinline__ void load_edge(const void* ei, int e, int is32, int& src, int& dst) {
    if (is32) {
        const int* p = (const int*)ei;
        src = p[e]; dst = p[NE + e];
    } else {
        const long long* p = (const long long*)ei;
        src = (int)p[e]; dst = (int)p[NE + e];
    }
}

// ---------------- CSR build ----------------
__global__ void k_zero_deg() {
    int i = blockIdx.x * blockDim.x + threadIdx.x;
    if (i < NN) g_cur[i] = 0;
}
__global__ void k_hist(const void* __restrict__ ei) {
    int e = blockIdx.x * blockDim.x + threadIdx.x;
    if (e >= NE) return;
    int src, dst;
    load_edge(ei, e, g_ei_is32, src, dst);
    if ((unsigned)src < NN && (unsigned)dst < NN) atomicAdd(&g_cur[dst], 1);
}
// 196 blocks x 256: per-block sum of degrees
__global__ void k_scan1() {
    __shared__ int s[256];
    int tid = threadIdx.x;
    int i = blockIdx.x * 256 + tid;
    s[tid] = (i < NN) ? g_cur[i] : 0;
    __syncthreads();
    for (int o = 128; o > 0; o >>= 1) {
        if (tid < o) s[tid] += s[tid + o];
        __syncthreads();
    }
    if (tid == 0) g_blksum[blockIdx.x] = s[0];
}
// 1 block: exclusive scan of block sums
__global__ void k_scan2(int nblk) {
    __shared__ int s[256];
    int tid = threadIdx.x;
    int v = (tid < nblk) ? g_blksum[tid] : 0;
    s[tid] = v;
    __syncthreads();
    for (int o = 1; o < 256; o <<= 1) {
        int t = (tid >= o) ? s[tid - o] : 0;
        __syncthreads();
        s[tid] += t;
        __syncthreads();
    }
    if (tid < nblk) g_blksum[tid] = s[tid] - v;   // exclusive
}
// per-block local scan + offset -> row_ptr and cursor init
__global__ void k_scan3() {
    __shared__ int s[256];
    int tid = threadIdx.x;
    int i = blockIdx.x * 256 + tid;
    int v = (i < NN) ? g_cur[i] : 0;
    s[tid] = v;
    __syncthreads();
    for (int o = 1; o < 256; o <<= 1) {
        int t = (tid >= o) ? s[tid - o] : 0;
        __syncthreads();
        s[tid] += t;
        __syncthreads();
    }
    int excl = g_blksum[blockIdx.x] + s[tid] - v;
    if (i < NN) {
        g_rp[i]  = excl;
        g_cur[i] = excl;
        if (i == NN - 1) g_rp[NN] = excl + v;
    }
}
__global__ void k_reorder(const void* __restrict__ ei) {
    int e = blockIdx.x * blockDim.x + threadIdx.x;
    if (e >= NE) return;
    int src, dst;
    load_edge(ei, e, g_ei_is32, src, dst);
    if ((unsigned)src < NN && (unsigned)dst < NN) {
        int pos = atomicAdd(&g_cur[dst], 1);
        if (pos < NE) g_srt[pos] = src;
    }
}

// ---------------- gather (layer 1): mean of x[src] per dst, written to g_agg ----------------
__global__ void k_gather_x(const float* __restrict__ x) {
    int n    = (blockIdx.x * blockDim.x + threadIdx.x) >> 5;
    int lane = threadIdx.x & 31;
    if (n >= NN) return;
    int beg = g_rp[n], end = g_rp[n + 1];
    float4 a = make_float4(0.f, 0.f, 0.f, 0.f);
    int i = beg;
    for (; i + 2 <= end; i += 2) {
        int s0 = g_srt[i], s1 = g_srt[i + 1];
        float4 v0 = *(const float4*)(x + (size_t)s0 * DI + lane * 4);
        float4 v1 = *(const float4*)(x + (size_t)s1 * DI + lane * 4);
        a.x += v0.x; a.y += v0.y; a.z += v0.z; a.w += v0.w;
        a.x += v1.x; a.y += v1.y; a.z += v1.z; a.w += v1.w;
    }
    if (i < end) {
        int s0 = g_srt[i];
        float4 v0 = *(const float4*)(x + (size_t)s0 * DI + lane * 4);
        a.x += v0.x; a.y += v0.y; a.z += v0.z; a.w += v0.w;
    }
    float inv = 1.0f / fmaxf((float)(end - beg), 1.0f);
    *(float4*)(g_agg + (size_t)n * DI + lane * 4) =
        make_float4(a.x * inv, a.y * inv, a.z * inv, a.w * inv);
}

// ---------------- gather (layer 2): mean of g_p[src] per dst -> g_agg (64d) ----------------
__global__ void k_gather_p() {
    int n    = (blockIdx.x * blockDim.x + threadIdx.x) >> 5;
    int lane = threadIdx.x & 31;
    if (n >= NN) return;
    int beg = g_rp[n], end = g_rp[n + 1];
    float2 a = make_float2(0.f, 0.f);
    int i = beg;
    for (; i + 2 <= end; i += 2) {
        int s0 = g_srt[i], s1 = g_srt[i + 1];
        float2 v0 = *(const float2*)(g_p + (size_t)s0 * DO + lane * 2);
        float2 v1 = *(const float2*)(g_p + (size_t)s1 * DO + lane * 2);
        a.x += v0.x + v1.x; a.y += v0.y + v1.y;
    }
    if (i < end) {
        int s0 = g_srt[i];
        float2 v0 = *(const float2*)(g_p + (size_t)s0 * DO + lane * 2);
        a.x += v0.x; a.y += v0.y;
    }
    float inv = 1.0f / fmaxf((float)(end - beg), 1.0f);
    *(float2*)(g_agg + (size_t)n * DO + lane * 2) = make_float2(a.x * inv, a.y * inv);
}

// ---------------- layer-1 fused GEMM: h = relu(mean @ Wl1^T + bl1 + x @ Wr1^T) ----------------
__global__ void __launch_bounds__(512, 1) k_gemm1(
    const float* __restrict__ x, const float* __restrict__ Wl,
    const float* __restrict__ bl, const float* __restrict__ Wr)
{
    extern __shared__ float smem[];
    float* sWl = smem;                  // [128][SPAD]
    float* sWr = sWl + DH * SPAD;       // [128][SPAD]
    float* sXm = sWr + DH * SPAD;       // [64][SPAD]
    float* sXx = sXm + 64 * SPAD;       // [64][SPAD]

    const int tid   = threadIdx.x;
    const int node0 = blockIdx.x * 64;
    const int r     = tid >> 5;
    const int k4    = (tid & 31) * 4;

    #pragma unroll
    for (int it = 0; it < 8; it++) {
        int j = it * 16 + r;
        *(float4*)(sWl + j * SPAD + k4) = *(const float4*)(Wl + j * DI + k4);
        *(float4*)(sWr + j * SPAD + k4) = *(const float4*)(Wr + j * DI + k4);
    }
    #pragma unroll
    for (int it = 0; it < 4; it++) {
        int nl = it * 16 + r;
        int n  = node0 + nl;
        float4 xm = make_float4(0.f, 0.f, 0.f, 0.f), xx = xm;
        if (n < NN) {
            xm = *(const float4*)(g_agg + (size_t)n * DI + k4);   // already the mean
            xx = *(const float4*)(x + (size_t)n * DI + k4);
        }
        *(float4*)(sXm + nl * SPAD + k4) = xm;
        *(float4*)(sXx + nl * SPAD + k4) = xx;
    }
    __syncthreads();

    const int lane = tid & 31;
    const int jl   = lane & 15;
    const int jo   = (r >> 3) * 4;
    const int nb   = ((r & 7) * 2 + (lane >> 4)) * 4;

    unsigned long long acc[4][4];
    #pragma unroll
    for (int nn = 0; nn < 4; nn++)
        #pragma unroll
        for (int jj = 0; jj < 4; jj++) acc[nn][jj] = 0ull;

    #pragma unroll 4
    for (int k = 0; k < DI; k += 4) {
        ulonglong2 xm[4], xx[4];
        #pragma unroll
        for (int nn = 0; nn < 4; nn++) {
            xm[nn] = *(const ulonglong2*)(sXm + (nb + nn) * SPAD + k);
            xx[nn] = *(const ulonglong2*)(sXx + (nb + nn) * SPAD + k);
        }
        #pragma unroll
        for (int jj = 0; jj < 4; jj++) {
            int j = jl + 16 * (jo + jj);
            ulonglong2 wl = *(const ulonglong2*)(sWl + j * SPAD + k);
            ulonglong2 wr = *(const ulonglong2*)(sWr + j * SPAD + k);
            #pragma unroll
            for (int nn = 0; nn < 4; nn++) {
                fma2(acc[nn][jj], xm[nn].x, wl.x);
                fma2(acc[nn][jj], xm[nn].y, wl.y);
                fma2(acc[nn][jj], xx[nn].x, wr.x);
                fma2(acc[nn][jj], xx[nn].y, wr.y);
            }
        }
    }

    #pragma unroll
    for (int nn = 0; nn < 4; nn++) {
        int n = node0 + nb + nn;
        if (n < NN) {
            #pragma unroll
            for (int jj = 0; jj < 4; jj++) {
                int j = jl + 16 * (jo + jj);
                float2 s = unpack2(acc[nn][jj]);
                float v = s.x + s.y + bl[j];
                g_h[(size_t)n * DH + j] = fmaxf(v, 0.0f);
            }
        }
    }
}

// ---------------- layer-2 GEMMs (in=128, out=64) ----------------
// FINAL=false: g_p = h @ Wl2^T
// FINAL=true : out = log_softmax(relu(mean_agg + bl2 + h @ Wr2^T))  (lsm fused)
template<bool FINAL>
__global__ void __launch_bounds__(256) k_gemmB(
    const float* __restrict__ W, const float* __restrict__ bias, float* __restrict__ out)
{
    extern __shared__ float smem[];
    float* sW = smem;                 // [64][SPAD]
    float* sX = sW + DO * SPAD;       // [64][SPAD]

    const int tid   = threadIdx.x;
    const int node0 = blockIdx.x * 64;
    const int r     = tid >> 5;
    const int k4    = (tid & 31) * 4;

    #pragma unroll
    for (int it = 0; it < 8; it++) {
        int j = it * 8 + r;
        *(float4*)(sW + j * SPAD + k4) = *(const float4*)(W + j * DH + k4);
        int n = node0 + j;
        float4 h4 = make_float4(0.f, 0.f, 0.f, 0.f);
        if (n < NN) h4 = *(const float4*)(g_h + (size_t)n * DH + k4);
        *(float4*)(sX + j * SPAD + k4) = h4;
    }
    __syncthreads();

    const int lane = tid & 31;
    const int jl   = lane & 15;
    const int nb   = ((tid >> 5) * 2 + (lane >> 4)) * 4;

    unsigned long long acc[4][4];
    #pragma unroll
    for (int nn = 0; nn < 4; nn++)
        #pragma unroll
        for (int jj = 0; jj < 4; jj++) acc[nn][jj] = 0ull;

    #pragma unroll 4
    for (int k = 0; k < DH; k += 4) {
        ulonglong2 xv[4];
        #pragma unroll
        for (int nn = 0; nn < 4; nn++)
            xv[nn] = *(const ulonglong2*)(sX + (nb + nn) * SPAD + k);
        #pragma unroll
        for (int jj = 0; jj < 4; jj++) {
            int j = jl + 16 * jj;
            ulonglong2 wv = *(const ulonglong2*)(sW + j * SPAD + k);
            #pragma unroll
            for (int nn = 0; nn < 4; nn++) {
                fma2(acc[nn][jj], xv[nn].x, wv.x);
                fma2(acc[nn][jj], xv[nn].y, wv.y);
            }
        }
    }

    #pragma unroll
    for (int nn = 0; nn < 4; nn++) {
        int n = node0 + nb + nn;
        bool valid = (n < NN);
        if (FINAL) {
            float v[4];
            #pragma unroll
            for (int jj = 0; jj < 4; jj++) {
                int j = jl + 16 * jj;
                float2 s = unpack2(acc[nn][jj]);
                float t = s.x + s.y;
                if (valid) t += g_agg[(size_t)n * DO + j] + bias[j];   // g_agg holds the mean
                v[jj] = valid ? fmaxf(t, 0.0f) : 0.0f;
            }
            float m = fmaxf(fmaxf(v[0], v[1]), fmaxf(v[2], v[3]));
            #pragma unroll
            for (int o = 8; o > 0; o >>= 1) m = fmaxf(m, __shfl_xor_sync(0xffffffffu, m, o));
            float ss = expf(v[0] - m) + expf(v[1] - m) + expf(v[2] - m) + expf(v[3] - m);
            #pragma unroll
            for (int o = 8; o > 0; o >>= 1) ss += __shfl_xor_sync(0xffffffffu, ss, o);
            float lse = m + logf(ss);
            if (valid) {
                #pragma unroll
                for (int jj = 0; jj < 4; jj++) {
                    int j = jl + 16 * jj;
                    out[(size_t)n * DO + j] = v[jj] - lse;
                }
            }
        } else {
            if (valid) {
                #pragma unroll
                for (int jj = 0; jj < 4; jj++) {
                    int j = jl + 16 * jj;
                    float2 s = unpack2(acc[nn][jj]);
                    g_p[(size_t)n * DO + j] = s.x + s.y;
                }
            }
        }
    }
}

// ---------------- launch ----------------
extern "C" void kernel_launch(void* const* d_in, const int* in_sizes, int n_in,
                              void* d_out, int out_size) {
    const float* x   = (const float*)d_in[0];
    const void*  ei  = d_in[1];
    const float* Wl1 = (const float*)d_in[2];
    const float* bl1 = (const float*)d_in[3];
    const float* Wr1 = (const float*)d_in[4];
    const float* Wl2 = (const float*)d_in[5];
    const float* bl2 = (const float*)d_in[6];
    const float* Wr2 = (const float*)d_in[7];
    float* out = (float*)d_out;

    const int SM1 = (2 * DH * SPAD + 2 * 64 * SPAD) * (int)sizeof(float);  // 202752 B
    const int SM2 = (2 * 64 * SPAD) * (int)sizeof(float);                  // 67584 B
    (void)cudaFuncSetAttribute(k_gemm1,        cudaFuncAttributeMaxDynamicSharedMemorySize, SM1);
    (void)cudaFuncSetAttribute(k_gemmB<false>, cudaFuncAttributeMaxDynamicSharedMemorySize, SM2);
    (void)cudaFuncSetAttribute(k_gemmB<true>,  cudaFuncAttributeMaxDynamicSharedMemorySize, SM2);

    const int GN   = (NN + 63) / 64;
    const int NBLK = (NN + 255) / 256;         // 196 scan blocks
    const int EB   = (NE + 255) / 256;         // 3125 edge blocks
    const int GW   = (NN * 32 + 255) / 256;    // warp-per-node blocks

    k_detect_ei<<<1, 1>>>(ei);
    // CSR build
    k_zero_deg<<<NBLK, 256>>>();
    k_hist<<<EB, 256>>>(ei);
    k_scan1<<<NBLK, 256>>>();
    k_scan2<<<1, 256>>>(NBLK);
    k_scan3<<<NBLK, 256>>>();
    k_reorder<<<EB, 256>>>(ei);
    // layer 1
    k_gather_x<<<GW, 256>>>(x);
    k_gemm1<<<GN, 512, SM1>>>(x, Wl1, bl1, Wr1);
    // layer 2
    k_gemmB<false><<<GN, 256, SM2>>>(Wl2, nullptr, nullptr);
    k_gather_p<<<GW, 256>>>();
    k_gemmB<true><<<GN, 256, SM2>>>(Wr2, bl2, out);
}